// round 10
// baseline (speedup 1.0000x reference)
#include <cuda_runtime.h>
#include <math_constants.h>

#define BB 32
#define SS 4096
#define HH 1024
#define KSPLIT 16
#define KCH (HH / KSPLIT)   // 64
#define BG 8                 // batches per v-worker block
#define HTW 256
#define NVBLK 256            // v-worker blocks (lbid < NVBLK)
#define NRED 128             // reducer blocks  (lbid < NRED)

// Scratch (allocation-free rule: __device__ globals; zero-initialized)
__device__ float g_vp[KSPLIT][BB * HH];   // split-K partials (2 MB)
__device__ float g_v[BB * HH];            // reduced v
__device__ unsigned int g_vcnt;           // v partials complete counter
__device__ unsigned int g_rdone;          // reducers complete counter
__device__ unsigned int g_ready;          // v ready flag (release/acquire)

__device__ __forceinline__ unsigned int ld_acq(const unsigned int* p) {
    unsigned int v;
    asm volatile("ld.acquire.gpu.u32 %0, [%1];" : "=r"(v) : "l"(p) : "memory");
    return v;
}
__device__ __forceinline__ void st_rel(unsigned int* p, unsigned int v) {
    asm volatile("st.release.gpu.u32 [%0], %1;" :: "l"(p), "r"(v) : "memory");
}
__device__ __forceinline__ void prefetch_l2(const void* p) {
    asm volatile("prefetch.global.L2 [%0];" :: "l"(p));
}

// ---------------------------------------------------------------------------
// Fused kernel: grid (128, 32) x 256 threads.
//  lbid < 256 : compute v = hid @ W partials (bias dropped: softmax shift-inv)
//  lbid < 128 : additionally reduce partials -> g_v, last sets g_ready
//  all others : prefetch their own enc tile into L2 while v completes
//  everyone   : wait g_ready, then R1's proven score loop (81us @ 84% DRAM)
// All v/reduce blocks have lbid < 256 < wave-1 size (>=5 blocks/SM at ~45
// regs), so they are resident before any spinner can starve them.
// ---------------------------------------------------------------------------
__global__ void __launch_bounds__(256) fused_k(const float* __restrict__ hidden,
                                               const float* __restrict__ W,
                                               const float* __restrict__ enc,
                                               float* __restrict__ out) {
    __shared__ float4 sv[HH / 4];           // staged v[b] for score phase
    __shared__ float sh[BG * KCH];          // staged hidden for v phase (2 KB)

    const int b   = blockIdx.y;
    const int tid = threadIdx.x;
    const unsigned int lbid = blockIdx.x + gridDim.x * blockIdx.y;
    const float* my_enc = enc + (size_t)b * SS * HH + (size_t)blockIdx.x * 32 * HH;

    if (lbid < NVBLK) {
        // ---------------- v partial phase ----------------
        const int hx = lbid & 3;
        const int ks = (lbid >> 2) & (KSPLIT - 1);
        const int bg = (lbid >> 6) & 3;
        const int k0 = ks * KCH;
        const int h  = hx * HTW + tid;

        for (int i = tid; i < BG * KCH; i += 256) {
            int j = i / KCH, k = i % KCH;
            sh[i] = hidden[(bg * BG + j) * HH + k0 + k];
        }
        __syncthreads();

        float acc[BG];
        #pragma unroll
        for (int j = 0; j < BG; j++) acc[j] = 0.f;

        #pragma unroll
        for (int kk = 0; kk < KCH; kk += 16) {
            float wv[16];
            #pragma unroll
            for (int u = 0; u < 16; u++)
                wv[u] = W[(size_t)(k0 + kk + u) * HH + h];
            #pragma unroll
            for (int u = 0; u < 16; u++)
                #pragma unroll
                for (int j = 0; j < BG; j++)
                    acc[j] += sh[j * KCH + kk + u] * wv[u];
        }
        #pragma unroll
        for (int j = 0; j < BG; j++)
            g_vp[ks][(bg * BG + j) * HH + h] = acc[j];

        __threadfence();
        __syncthreads();
        if (tid == 0) atomicAdd(&g_vcnt, 1u);

        if (lbid < NRED) {
            // ------------- reduction phase (blocks 0..127) -------------
            if (tid == 0) {
                while (ld_acq(&g_vcnt) < NVBLK) __nanosleep(64);
            }
            __syncthreads();
            const int o = lbid * 256 + tid;      // covers all BB*HH outputs
            float s = 0.f;
            #pragma unroll
            for (int p = 0; p < KSPLIT; p++) s += __ldcg(&g_vp[p][o]);
            g_v[o] = s;
            __threadfence();
            __syncthreads();
            if (tid == 0) {
                if (atomicAdd(&g_rdone, 1u) == NRED - 1u)
                    st_rel(&g_ready, 1u);
            }
        } else {
            // non-reducing v blocks: prefetch own enc tile while reduce runs
            for (int i = tid; i < 1024; i += 256)
                prefetch_l2(my_enc + i * 32);    // one 128B line each
        }
    } else {
        // ---------------- prefetch phase (all non-v blocks) ----------------
        // 32 rows x 4KB = 1024 cache lines into L2 while v is computed.
        for (int i = tid; i < 1024; i += 256)
            prefetch_l2(my_enc + i * 32);
    }

    // ---------------- wait for v ----------------
    if (tid == 0) {
        while (ld_acq(&g_ready) == 0u) __nanosleep(128);
    }
    __syncthreads();

    // ---------------- score phase: exact R1 structure ----------------
    for (int i = tid; i < HH / 4; i += 256)
        sv[i] = reinterpret_cast<const float4*>(g_v + b * HH)[i];
    __syncthreads();

    const int w = tid >> 5, lane = tid & 31;
    const int s0 = blockIdx.x * 32 + w * 4;

    #pragma unroll
    for (int r = 0; r < 4; r++) {
        const int s = s0 + r;
        const float4* row =
            reinterpret_cast<const float4*>(enc + (size_t)b * SS * HH + (size_t)s * HH);
        float acc = 0.f;
        #pragma unroll
        for (int i = 0; i < 8; i++) {
            float4 e = row[lane + i * 32];
            float4 v = sv[lane + i * 32];
            acc += e.x * v.x + e.y * v.y + e.z * v.z + e.w * v.w;
        }
        #pragma unroll
        for (int o = 16; o; o >>= 1) acc += __shfl_xor_sync(0xffffffffu, acc, o);
        if (lane == 0) out[b * SS + s] = acc;
    }
}

// ---------------------------------------------------------------------------
// Softmax in place over each row of 4096. grid BB, block 1024.
// Block 0 also resets the fused kernel's sync words for the next graph replay.
// ---------------------------------------------------------------------------
__global__ void softmax_k(float* __restrict__ out) {
    __shared__ float red[32];
    __shared__ float bcast;
    if (blockIdx.x == 0 && threadIdx.x == 0) {
        g_vcnt = 0u;
        g_rdone = 0u;
        g_ready = 0u;
    }
    float* row = out + blockIdx.x * SS;
    const int w = threadIdx.x >> 5, lane = threadIdx.x & 31;

    float vals[4];
    float mx = -CUDART_INF_F;
    #pragma unroll
    for (int i = 0; i < 4; i++) {
        vals[i] = row[threadIdx.x + i * 1024];
        mx = fmaxf(mx, vals[i]);
    }
    #pragma unroll
    for (int o = 16; o; o >>= 1) mx = fmaxf(mx, __shfl_xor_sync(0xffffffffu, mx, o));
    if (lane == 0) red[w] = mx;
    __syncthreads();
    if (w == 0) {
        float m = red[lane];
        #pragma unroll
        for (int o = 16; o; o >>= 1) m = fmaxf(m, __shfl_xor_sync(0xffffffffu, m, o));
        if (lane == 0) bcast = m;
    }
    __syncthreads();
    mx = bcast;

    float sum = 0.f;
    #pragma unroll
    for (int i = 0; i < 4; i++) {
        vals[i] = __expf(vals[i] - mx);
        sum += vals[i];
    }
    #pragma unroll
    for (int o = 16; o; o >>= 1) sum += __shfl_xor_sync(0xffffffffu, sum, o);
    if (lane == 0) red[w] = sum;
    __syncthreads();
    if (w == 0) {
        float s = red[lane];
        #pragma unroll
        for (int o = 16; o; o >>= 1) s += __shfl_xor_sync(0xffffffffu, s, o);
        if (lane == 0) bcast = s;
    }
    __syncthreads();
    const float inv = 1.0f / bcast;

    #pragma unroll
    for (int i = 0; i < 4; i++)
        row[threadIdx.x + i * 1024] = vals[i] * inv;
}

extern "C" void kernel_launch(void* const* d_in, const int* in_sizes, int n_in,
                              void* d_out, int out_size) {
    const float* hidden = (const float*)d_in[0];  // [B,1,H]
    const float* enc    = (const float*)d_in[1];  // [B,S,H]
    const float* W      = (const float*)d_in[2];  // [H,H]
    // d_in[3] = bias — unused: constant per row under softmax
    float* out = (float*)d_out;                   // [B,S]

    fused_k<<<dim3(SS / 32, BB), 256>>>(hidden, W, enc, out);
    softmax_k<<<BB, 1024>>>(out);
}

// round 11
// speedup vs baseline: 1.0462x; 1.0462x over previous
#include <cuda_runtime.h>
#include <math_constants.h>

#define BB 32
#define SS 4096
#define HH 1024
#define KSPLIT 64
#define KCH (HH / KSPLIT)   // 16
#define HX 4
#define HTW 256
#define NVBLK 256            // v-worker blocks (lbid < NVBLK)

// Scratch (allocation-free rule: __device__ globals; zero-initialized)
__device__ float g_vp[KSPLIT][BB * HH];   // split-K partials (8 MB, L2-resident)
__device__ float g_v[BB * HH];            // reduced v
__device__ unsigned int g_vcnt;           // v partials complete counter
__device__ unsigned int g_ready[BB];      // per-batch v-ready flags

__device__ __forceinline__ unsigned int ld_acq(const unsigned int* p) {
    unsigned int v;
    asm volatile("ld.acquire.gpu.u32 %0, [%1];" : "=r"(v) : "l"(p) : "memory");
    return v;
}
__device__ __forceinline__ void st_rel(unsigned int* p, unsigned int v) {
    asm volatile("st.release.gpu.u32 [%0], %1;" :: "l"(p), "r"(v) : "memory");
}

// ---------------------------------------------------------------------------
// Fused kernel: grid (128, 32) x 256 threads, ~66 regs -> 3 blocks/SM
// -> wave 1 holds >= 444 linear bids, so all 256 v-workers are resident.
//  lbid < 256 : v = hid @ W split-K partials (R9's best-measured shape)
//  lbid < 32  : then reduce batch lbid's 1024 values, st.release g_ready[lbid]
//  everyone   : wait g_ready[own batch] only (staggered ramp), then R1's
//               proven score loop (81us @ 84% DRAM). No prefetch (R10 lesson).
// bias dropped: softmax is shift-invariant.
// ---------------------------------------------------------------------------
__global__ void __launch_bounds__(256, 3) fused_k(const float* __restrict__ hidden,
                                                  const float* __restrict__ W,
                                                  const float* __restrict__ enc,
                                                  float* __restrict__ out) {
    __shared__ float4 sv[HH / 4];           // staged v[b] for score phase
    __shared__ float sh[KCH * BB];          // staged hidden for v phase (2 KB)

    const int b   = blockIdx.y;
    const int tid = threadIdx.x;
    const unsigned int lbid = blockIdx.x + gridDim.x * blockIdx.y;

    if (lbid < NVBLK) {
        // ---------------- v partial phase (R9 shape) ----------------
        const int hx = lbid & 3;
        const int ks = lbid >> 2;            // 0..63
        const int k0 = ks * KCH;
        const int h  = hx * HTW + tid;

        for (int i = tid; i < KCH * BB; i += 256) {
            int k = i / BB, bb = i % BB;
            sh[i] = hidden[bb * HH + k0 + k];
        }
        __syncthreads();

        float wv[KCH];
        #pragma unroll
        for (int u = 0; u < KCH; u++)
            wv[u] = W[(size_t)(k0 + u) * HH + h];

        float acc[BB];
        #pragma unroll
        for (int j = 0; j < BB; j++) acc[j] = 0.f;

        #pragma unroll
        for (int u = 0; u < KCH; u++) {
            const float4* hb4 = reinterpret_cast<const float4*>(&sh[u * BB]);
            #pragma unroll
            for (int j = 0; j < BB / 4; j++) {
                float4 hv = hb4[j];          // broadcast LDS.128
                acc[j * 4 + 0] += hv.x * wv[u];
                acc[j * 4 + 1] += hv.y * wv[u];
                acc[j * 4 + 2] += hv.z * wv[u];
                acc[j * 4 + 3] += hv.w * wv[u];
            }
        }
        #pragma unroll
        for (int j = 0; j < BB; j++)
            g_vp[ks][j * HH + h] = acc[j];

        __threadfence();
        __syncthreads();
        if (tid == 0) atomicAdd(&g_vcnt, 1u);

        if (lbid < BB) {
            // ------- reduce batch r = lbid; publish its ready flag -------
            const int r = lbid;
            if (tid == 0) {
                while (ld_acq(&g_vcnt) < NVBLK) __nanosleep(64);
            }
            __syncthreads();
            #pragma unroll
            for (int j = 0; j < 4; j++) {
                const int idx = r * HH + tid + j * 256;
                float s = 0.f;
                #pragma unroll
                for (int p = 0; p < KSPLIT; p++) s += __ldcg(&g_vp[p][idx]);
                g_v[idx] = s;
            }
            __threadfence();
            __syncthreads();
            if (tid == 0) st_rel(&g_ready[r], 1u);
        }
    }

    // ---------------- wait only for our own batch's v ----------------
    if (tid == 0) {
        while (ld_acq(&g_ready[b]) == 0u) __nanosleep(64);
    }
    __syncthreads();

    // ---------------- score phase: exact R1 structure ----------------
    for (int i = tid; i < HH / 4; i += 256)
        sv[i] = reinterpret_cast<const float4*>(g_v + b * HH)[i];
    __syncthreads();

    const int w = tid >> 5, lane = tid & 31;
    const int s0 = blockIdx.x * 32 + w * 4;

    #pragma unroll
    for (int r = 0; r < 4; r++) {
        const int s = s0 + r;
        const float4* row =
            reinterpret_cast<const float4*>(enc + (size_t)b * SS * HH + (size_t)s * HH);
        float acc = 0.f;
        #pragma unroll
        for (int i = 0; i < 8; i++) {
            float4 e = row[lane + i * 32];
            float4 v = sv[lane + i * 32];
            acc += e.x * v.x + e.y * v.y + e.z * v.z + e.w * v.w;
        }
        #pragma unroll
        for (int o = 16; o; o >>= 1) acc += __shfl_xor_sync(0xffffffffu, acc, o);
        if (lane == 0) out[b * SS + s] = acc;
    }
}

// ---------------------------------------------------------------------------
// Softmax in place over each row of 4096. grid BB, block 1024.
// Also resets the fused kernel's sync words for the next graph replay
// (fused_k has fully completed before this kernel starts).
// ---------------------------------------------------------------------------
__global__ void softmax_k(float* __restrict__ out) {
    __shared__ float red[32];
    __shared__ float bcast;
    if (blockIdx.x == 0) {
        if (threadIdx.x == 0) g_vcnt = 0u;
        if (threadIdx.x < BB) g_ready[threadIdx.x] = 0u;
    }
    float* row = out + blockIdx.x * SS;
    const int w = threadIdx.x >> 5, lane = threadIdx.x & 31;

    float vals[4];
    float mx = -CUDART_INF_F;
    #pragma unroll
    for (int i = 0; i < 4; i++) {
        vals[i] = row[threadIdx.x + i * 1024];
        mx = fmaxf(mx, vals[i]);
    }
    #pragma unroll
    for (int o = 16; o; o >>= 1) mx = fmaxf(mx, __shfl_xor_sync(0xffffffffu, mx, o));
    if (lane == 0) red[w] = mx;
    __syncthreads();
    if (w == 0) {
        float m = red[lane];
        #pragma unroll
        for (int o = 16; o; o >>= 1) m = fmaxf(m, __shfl_xor_sync(0xffffffffu, m, o));
        if (lane == 0) bcast = m;
    }
    __syncthreads();
    mx = bcast;

    float sum = 0.f;
    #pragma unroll
    for (int i = 0; i < 4; i++) {
        vals[i] = __expf(vals[i] - mx);
        sum += vals[i];
    }
    #pragma unroll
    for (int o = 16; o; o >>= 1) sum += __shfl_xor_sync(0xffffffffu, sum, o);
    if (lane == 0) red[w] = sum;
    __syncthreads();
    if (w == 0) {
        float s = red[lane];
        #pragma unroll
        for (int o = 16; o; o >>= 1) s += __shfl_xor_sync(0xffffffffu, s, o);
        if (lane == 0) bcast = s;
    }
    __syncthreads();
    const float inv = 1.0f / bcast;

    #pragma unroll
    for (int i = 0; i < 4; i++)
        row[threadIdx.x + i * 1024] = vals[i] * inv;
}

extern "C" void kernel_launch(void* const* d_in, const int* in_sizes, int n_in,
                              void* d_out, int out_size) {
    const float* hidden = (const float*)d_in[0];  // [B,1,H]
    const float* enc    = (const float*)d_in[1];  // [B,S,H]
    const float* W      = (const float*)d_in[2];  // [H,H]
    // d_in[3] = bias — unused: constant per row under softmax
    float* out = (float*)d_out;                   // [B,S]

    fused_k<<<dim3(SS / 32, BB), 256>>>(hidden, W, enc, out);
    softmax_k<<<BB, 1024>>>(out);
}

// round 12
// speedup vs baseline: 1.0677x; 1.0206x over previous
#include <cuda_runtime.h>
#include <math_constants.h>

#define BB 32
#define SS 4096
#define HH 1024
#define KSPLIT 64
#define KCH (HH / KSPLIT)   // 16
#define HX 4                 // h-tiles of 256
#define HTW 256              // h-tile width

// Scratch (allocation-free rule: __device__ globals; zero-initialized)
__device__ float g_vp[KSPLIT][BB * HH];   // split-K partials of v = hid @ W (8 MB)
__device__ float g_v[BB * HH];            // reduced v
__device__ unsigned int g_vcnt[HX];       // partials-complete counters
__device__ unsigned int g_vdone[HX];      // reduction-complete counters (for reset)

// ---------------------------------------------------------------------------
// v = hid @ W (R9 shape — best measured). Split-K partials + spin reduction.
// grid (4, 64) = 256 blocks x 256 thr, all resident -> spin cannot deadlock.
// bias term dropped (softmax is shift-invariant).
// ---------------------------------------------------------------------------
__global__ void __launch_bounds__(256) v_k(const float* __restrict__ hidden,
                                           const float* __restrict__ W) {
    __shared__ float sh[KCH * BB];  // [k][b], 2 KB
    const int hx = blockIdx.x;
    const int ks = blockIdx.y;
    const int k0 = ks * KCH;
    const int h  = hx * HTW + threadIdx.x;

    for (int i = threadIdx.x; i < KCH * BB; i += 256) {
        int k = i / BB, b = i % BB;
        sh[i] = hidden[b * HH + k0 + k];
    }
    __syncthreads();

    float wv[KCH];
    #pragma unroll
    for (int u = 0; u < KCH; u++)
        wv[u] = W[(size_t)(k0 + u) * HH + h];

    float acc[BB];
    #pragma unroll
    for (int b = 0; b < BB; b++) acc[b] = 0.f;

    #pragma unroll
    for (int u = 0; u < KCH; u++) {
        const float4* hb4 = reinterpret_cast<const float4*>(&sh[u * BB]);
        #pragma unroll
        for (int j = 0; j < BB / 4; j++) {
            float4 hv = hb4[j];                       // broadcast LDS.128
            acc[j * 4 + 0] += hv.x * wv[u];
            acc[j * 4 + 1] += hv.y * wv[u];
            acc[j * 4 + 2] += hv.z * wv[u];
            acc[j * 4 + 3] += hv.w * wv[u];
        }
    }
    #pragma unroll
    for (int b = 0; b < BB; b++)
        g_vp[ks][b * HH + h] = acc[b];

    __threadfence();
    __syncthreads();
    if (threadIdx.x == 0) {
        atomicAdd(&g_vcnt[hx], 1u);
        unsigned int c;
        do {
            asm volatile("ld.acquire.gpu.u32 %0, [%1];"
                         : "=r"(c) : "l"(&g_vcnt[hx]) : "memory");
            if (c < KSPLIT) __nanosleep(64);
        } while (c < KSPLIT);
    }
    __syncthreads();

    if (ks < BB) {
        const int idx = ks * HH + h;
        float s = 0.f;
        #pragma unroll
        for (int p = 0; p < KSPLIT; p++) s += __ldcg(&g_vp[p][idx]);
        g_v[idx] = s;
        __threadfence();
    }

    __syncthreads();
    if (threadIdx.x == 0) {
        if (atomicAdd(&g_vdone[hx], 1u) == KSPLIT - 1u) {
            g_vcnt[hx] = 0u;
            g_vdone[hx] = 0u;
        }
    }
}

// ---------------------------------------------------------------------------
// Energies — R1 structure with 2-row interleaving: each pass streams two
// independent rows (16 outstanding 128B loads/warp instead of 8), so one
// row's FMA/shuffle/STG hides the other's loads. Targets the per-row memory
// bubble that held R1 at 84.3% DRAM.
// grid (SS/32, BB) = (128, 32), block 256 = 8 warps x 4 rows/warp.
// ---------------------------------------------------------------------------
__global__ void __launch_bounds__(256) score_k(const float* __restrict__ enc,
                                               float* __restrict__ out) {
    __shared__ float4 sv[HH / 4];  // v[b] staged, 4 KB
    const int b = blockIdx.y;
    for (int i = threadIdx.x; i < HH / 4; i += 256)
        sv[i] = reinterpret_cast<const float4*>(g_v + b * HH)[i];
    __syncthreads();

    const int w = threadIdx.x >> 5, lane = threadIdx.x & 31;
    const int s0 = blockIdx.x * 32 + w * 4;
    const float4* base = reinterpret_cast<const float4*>(enc + (size_t)b * SS * HH);

    #pragma unroll
    for (int rp = 0; rp < 2; rp++) {
        const int sA = s0 + rp * 2;
        const int sB = sA + 1;
        const float4* rowA = base + (size_t)sA * (HH / 4);
        const float4* rowB = base + (size_t)sB * (HH / 4);

        float accA = 0.f, accB = 0.f;
        #pragma unroll
        for (int i = 0; i < 8; i++) {
            float4 a = rowA[lane + i * 32];
            float4 c = rowB[lane + i * 32];
            float4 v = sv[lane + i * 32];
            accA += a.x * v.x + a.y * v.y + a.z * v.z + a.w * v.w;
            accB += c.x * v.x + c.y * v.y + c.z * v.z + c.w * v.w;
        }
        #pragma unroll
        for (int o = 16; o; o >>= 1) {
            accA += __shfl_xor_sync(0xffffffffu, accA, o);
            accB += __shfl_xor_sync(0xffffffffu, accB, o);
        }
        if (lane == 0) {
            out[b * SS + sA] = accA;
            out[b * SS + sB] = accB;
        }
    }
}

// ---------------------------------------------------------------------------
// Softmax in place over each row of 4096. grid BB, block 1024, 4 elems/thread.
// ---------------------------------------------------------------------------
__global__ void softmax_k(float* __restrict__ out) {
    __shared__ float red[32];
    __shared__ float bcast;
    float* row = out + blockIdx.x * SS;
    const int w = threadIdx.x >> 5, lane = threadIdx.x & 31;

    float vals[4];
    float mx = -CUDART_INF_F;
    #pragma unroll
    for (int i = 0; i < 4; i++) {
        vals[i] = row[threadIdx.x + i * 1024];
        mx = fmaxf(mx, vals[i]);
    }
    #pragma unroll
    for (int o = 16; o; o >>= 1) mx = fmaxf(mx, __shfl_xor_sync(0xffffffffu, mx, o));
    if (lane == 0) red[w] = mx;
    __syncthreads();
    if (w == 0) {
        float m = red[lane];
        #pragma unroll
        for (int o = 16; o; o >>= 1) m = fmaxf(m, __shfl_xor_sync(0xffffffffu, m, o));
        if (lane == 0) bcast = m;
    }
    __syncthreads();
    mx = bcast;

    float sum = 0.f;
    #pragma unroll
    for (int i = 0; i < 4; i++) {
        vals[i] = __expf(vals[i] - mx);
        sum += vals[i];
    }
    #pragma unroll
    for (int o = 16; o; o >>= 1) sum += __shfl_xor_sync(0xffffffffu, sum, o);
    if (lane == 0) red[w] = sum;
    __syncthreads();
    if (w == 0) {
        float s = red[lane];
        #pragma unroll
        for (int o = 16; o; o >>= 1) s += __shfl_xor_sync(0xffffffffu, s, o);
        if (lane == 0) bcast = s;
    }
    __syncthreads();
    const float inv = 1.0f / bcast;

    #pragma unroll
    for (int i = 0; i < 4; i++)
        row[threadIdx.x + i * 1024] = vals[i] * inv;
}

extern "C" void kernel_launch(void* const* d_in, const int* in_sizes, int n_in,
                              void* d_out, int out_size) {
    const float* hidden = (const float*)d_in[0];  // [B,1,H]
    const float* enc    = (const float*)d_in[1];  // [B,S,H]
    const float* W      = (const float*)d_in[2];  // [H,H]
    // d_in[3] = bias — unused: constant per row under softmax
    float* out = (float*)d_out;                   // [B,S]

    v_k<<<dim3(HX, KSPLIT), 256>>>(hidden, W);
    score_k<<<dim3(SS / 32, BB), 256>>>(enc, out);
    softmax_k<<<BB, 1024>>>(out);
}